// round 2
// baseline (speedup 1.0000x reference)
#include <cuda_runtime.h>
#include <cuda_bf16.h>
#include <math.h>

// Problem constants
#define NB 2
#define NN 256
#define NC 5
#define NHID 32
#define NH 4
#define NDH 8
#define NFF 20

// Scratch (device globals: no allocation allowed)
__device__ float    g_q0[NB*NN*NHID];
__device__ float    g_yk[NB*NN*NHID];
__device__ float    g_yv[NB*NN*NHID];
__device__ unsigned g_adjbits[NB*NN*8];
__device__ unsigned g_adjmbits[NB*NN*8];
__device__ float    g_pooled[NB*NC];
__device__ int      g_adjmode;   // 0=uint8, 1=int32, 2=float32

__device__ __forceinline__ float gelu_t(float x){
    float x3 = x*x*x;
    float t = tanhf(0.7978845608028654f*(x + 0.044715f*x3));
    return 0.5f*x*(1.0f+t);
}
__device__ __forceinline__ float wredsum(float v){
    #pragma unroll
    for (int o=16;o;o>>=1) v += __shfl_xor_sync(0xffffffffu, v, o);
    return v;
}
__device__ __forceinline__ float wredmax(float v){
    #pragma unroll
    for (int o=16;o;o>>=1) v = fmaxf(v, __shfl_xor_sync(0xffffffffu, v, o));
    return v;
}

// ---------------------------------------------------------------------------
// Kernel A0: detect adjacency storage dtype by byte-lane signature.
// int32 0/1:   nonzero bytes only at offset%4==0
// float32 1.0: bytes [00 00 80 3F] -> nonzero only at offset%4 in {2,3}
// uint8 0/1:   nonzero bytes at all offsets (~6% density)
__global__ void detect_adj(const unsigned char* __restrict__ a){
    __shared__ int cnt[4];
    if (threadIdx.x < 4) cnt[threadIdx.x] = 0;
    __syncthreads();
    // scan only NB*NN*NN bytes: safe under every candidate dtype
    for (int i = threadIdx.x; i < NB*NN*NN; i += blockDim.x)
        if (a[i]) atomicAdd(&cnt[i & 3], 1);
    __syncthreads();
    if (threadIdx.x == 0){
        int mode;
        if (cnt[1]==0 && cnt[2]==0 && cnt[3]==0) mode = 1;      // int32
        else if (cnt[0]==0 && cnt[1]==0)         mode = 2;      // float32
        else                                     mode = 0;      // uint8
        g_adjmode = mode;
    }
}

// Kernel A1: pack adjacency -> bitmask rows (dtype-agnostic)
__global__ void pack_adj(const void* __restrict__ adjraw){
    int row = blockIdx.x;                 // b*256+i
    int tid = threadIdx.x;                // j
    int lane = tid & 31, wp = tid >> 5;
    int mode = g_adjmode;
    long idx = (long)row*NN + tid;
    bool v;
    if (mode == 1)      v = ((const int*)adjraw)[idx] != 0;
    else if (mode == 2) v = ((const float*)adjraw)[idx] != 0.f;
    else                v = ((const unsigned char*)adjraw)[idx] != 0;
    unsigned bal = __ballot_sync(0xffffffffu, v);
    if (lane == 0) g_adjbits[row*8 + wp] = bal;
}

// Kernel A2: adjm = adj | (adj@adj>0) | eye (bitwise)
__global__ void adjm_sq(){
    int row = blockIdx.x;
    int b = row >> 8, i = row & 255;
    int tid = threadIdx.x;
    __shared__ unsigned sm[8];
    if (tid < 8){
        unsigned v = g_adjbits[row*8 + tid];
        if (tid == (i >> 5)) v |= (1u << (i & 31));   // eye
        sm[tid] = v;
    }
    __syncthreads();
    bool nb = (g_adjbits[row*8 + (tid>>5)] >> (tid&31)) & 1u;
    if (nb){
        int jr = (b << 8) + tid;
        #pragma unroll
        for (int w=0; w<8; w++) atomicOr(&sm[w], g_adjbits[jr*8 + w]);
    }
    __syncthreads();
    if (tid < 8) g_adjmbits[row*8 + tid] = sm[tid];
}

// ---------------------------------------------------------------------------
// Kernel B: per-node norm_se3 (scalar path) + q0/yk/yv projections, zero pooled
__global__ void node_pre(const float* __restrict__ feats,
                         const float* __restrict__ Wq,   // Wq[0]: (5,32)
                         const float* __restrict__ Mk,   // Mk[0]: (5,32)
                         const float* __restrict__ Mv,   // Mv[0]: (5,32)
                         const float* __restrict__ gnA,  // gnA[0]: (5,)
                         const float* __restrict__ bnA){
    int idx = blockIdx.x*256 + threadIdx.x;
    if (idx < NB*NC) g_pooled[idx] = 0.f;
    if (idx >= NB*NN) return;
    float xv[NC], n0[NC];
    float mu = 0.f;
    #pragma unroll
    for (int c=0;c<NC;c++){ xv[c]=feats[idx*NC+c]; n0[c]=fabsf(xv[c]); mu += n0[c]; }
    mu *= 0.2f;
    float var = 0.f;
    #pragma unroll
    for (int c=0;c<NC;c++){ float d=n0[c]-mu; var = fmaf(d,d,var); }
    var *= 0.2f;
    float sd = sqrtf(var) + 1e-8f;
    float y[NC];
    #pragma unroll
    for (int c=0;c<NC;c++){
        float ln = (n0[c]-mu)/sd * gnA[c] + bnA[c];
        float g = gelu_t(ln);
        y[c] = (xv[c] > 0.f) ? g : ((xv[c] < 0.f) ? -g : 0.f);
    }
    #pragma unroll 8
    for (int hd=0; hd<NHID; hd++){
        float q=0.f,k=0.f,v=0.f;
        #pragma unroll
        for (int c=0;c<NC;c++){
            q = fmaf(y[c], Wq[c*NHID+hd], q);
            k = fmaf(y[c], Mk[c*NHID+hd], k);
            v = fmaf(y[c], Mv[c*NHID+hd], v);
        }
        g_q0[idx*NHID+hd]=q; g_yk[idx*NHID+hd]=k; g_yv[idx*NHID+hd]=v;
    }
}

// ---------------------------------------------------------------------------
// Kernel C: one block per (b,i) row.
// Compacted edge MLP -> logits -> masked softmax -> o0 -> Wo0 -> residual ->
// norm_se3 -> FF -> residual -> pooled atomicAdd.
__global__ void __launch_bounds__(256)
attn_row(const float* __restrict__ feats, const float* __restrict__ coors,
         const float* __restrict__ R1,  const float* __restrict__ rb1,
         const float* __restrict__ R2,  const float* __restrict__ rb2,
         const float* __restrict__ Wo0,
         const float* __restrict__ gnF, const float* __restrict__ bnF,
         const float* __restrict__ Wf1, const float* __restrict__ Wf2){
    __shared__ float shR2k[1024], shR2v[1024];                 // (32 t) x (32 hd)
    __shared__ float shR1[32], shrb1[32], shrb2k[32], shrb2v[32], shq[32];
    __shared__ unsigned shadj[8];
    __shared__ int shwcnt[8];
    __shared__ unsigned char shlist[256];
    __shared__ float shred[8][4];
    __shared__ float shmax[4], shsum[4];
    __shared__ float shpart[8][32];
    __shared__ float sho[32];
    __shared__ float shx[5];

    int row = blockIdx.x;
    int b = row >> 8;
    int tid = threadIdx.x;
    int lane = tid & 31, wp = tid >> 5;

    for (int s=tid; s<1024; s+=256){
        int t = s >> 5, hd = s & 31;
        shR2k[s] = R2[t*384 + hd];
        shR2v[s] = R2[t*384 + 192 + hd];
    }
    if (tid < 32){
        shR1[tid]=R1[tid]; shrb1[tid]=rb1[tid];
        shrb2k[tid]=rb2[tid]; shrb2v[tid]=rb2[192+tid];
        shq[tid]=g_q0[row*NHID+tid];
    }
    if (tid < 8) shadj[tid] = g_adjmbits[row*8+tid];
    __syncthreads();

    // deterministic compaction of active j's (ascending order)
    bool ok = (shadj[tid>>5] >> (tid&31)) & 1u;
    unsigned bal = __ballot_sync(0xffffffffu, ok);
    if (lane == 0) shwcnt[wp] = __popc(bal);
    __syncthreads();
    int base = 0, M = 0;
    #pragma unroll
    for (int w=0; w<8; w++){ if (w < wp) base += shwcnt[w]; M += shwcnt[w]; }
    if (ok) shlist[base + __popc(bal & ((1u<<lane)-1u))] = (unsigned char)tid;
    __syncthreads();

    bool act = tid < M;
    int j = act ? (int)shlist[tid] : 0;

    float lg[4] = {-1e9f,-1e9f,-1e9f,-1e9f};
    float vv[32];
    #pragma unroll
    for (int hd=0; hd<32; hd++) vv[hd] = 0.f;

    float cx = coors[row*3+0], cy = coors[row*3+1], cz = coors[row*3+2];

    if (act){
        int jr = (b << 8) + j;
        float dx = cx - coors[jr*3+0];
        float dy = cy - coors[jr*3+1];
        float dz = cz - coors[jr*3+2];
        float dist = sqrtf(fmaf(dx,dx,fmaf(dy,dy,fmaf(dz,dz,1e-12f))));
        float k0[32], v0[32];
        #pragma unroll
        for (int hd=0; hd<32; hd++){ k0[hd]=shrb2k[hd]; v0[hd]=shrb2v[hd]; }
        #pragma unroll 4
        for (int t=0; t<32; t++){
            float h = fmaxf(fmaf(dist, shR1[t], shrb1[t]), 0.f);
            const float4* wk = (const float4*)&shR2k[t*32];
            const float4* wv = (const float4*)&shR2v[t*32];
            #pragma unroll
            for (int c=0; c<8; c++){
                float4 a = wk[c];
                k0[4*c+0]=fmaf(h,a.x,k0[4*c+0]); k0[4*c+1]=fmaf(h,a.y,k0[4*c+1]);
                k0[4*c+2]=fmaf(h,a.z,k0[4*c+2]); k0[4*c+3]=fmaf(h,a.w,k0[4*c+3]);
                float4 bb = wv[c];
                v0[4*c+0]=fmaf(h,bb.x,v0[4*c+0]); v0[4*c+1]=fmaf(h,bb.y,v0[4*c+1]);
                v0[4*c+2]=fmaf(h,bb.z,v0[4*c+2]); v0[4*c+3]=fmaf(h,bb.w,v0[4*c+3]);
            }
        }
        const float* ykj = g_yk + jr*NHID;
        const float* yvj = g_yv + jr*NHID;
        float l[4] = {0.f,0.f,0.f,0.f};
        #pragma unroll
        for (int hd=0; hd<32; hd++)
            l[hd>>3] = fmaf(shq[hd]*ykj[hd], k0[hd], l[hd>>3]);
        #pragma unroll
        for (int h=0; h<4; h++) lg[h] = l[h]*0.35355339059327373f;  // 1/sqrt(8)
        #pragma unroll
        for (int hd=0; hd<32; hd++) vv[hd] = v0[hd]*yvj[hd];
    }

    // masked softmax over active j's (per head)
    float m[4];
    #pragma unroll
    for (int h=0; h<4; h++) m[h] = wredmax(lg[h]);
    if (lane == 0){
        #pragma unroll
        for (int h=0; h<4; h++) shred[wp][h] = m[h];
    }
    __syncthreads();
    if (tid < 4){
        float mm = -1e9f;
        #pragma unroll
        for (int w=0; w<8; w++) mm = fmaxf(mm, shred[w][tid]);
        shmax[tid] = mm;
    }
    __syncthreads();
    float e[4];
    #pragma unroll
    for (int h=0; h<4; h++) e[h] = act ? __expf(lg[h]-shmax[h]) : 0.f;
    float s[4];
    #pragma unroll
    for (int h=0; h<4; h++) s[h] = wredsum(e[h]);
    if (lane == 0){
        #pragma unroll
        for (int h=0; h<4; h++) shred[wp][h] = s[h];
    }
    __syncthreads();
    if (tid < 4){
        float ss = 0.f;
        #pragma unroll
        for (int w=0; w<8; w++) ss += shred[w][tid];
        shsum[tid] = ss;
    }
    __syncthreads();
    float a4[4];
    #pragma unroll
    for (int h=0; h<4; h++) a4[h] = e[h]/shsum[h];

    // o0[hd] = sum_j attn * vv
    #pragma unroll
    for (int hd=0; hd<32; hd++){
        float o = a4[hd>>3]*vv[hd];
        o = wredsum(o);
        if (lane == 0) shpart[wp][hd] = o;
    }
    __syncthreads();
    if (tid < 32){
        float o = 0.f;
        #pragma unroll
        for (int w=0; w<8; w++) o += shpart[w][tid];
        sho[tid] = o;
    }
    __syncthreads();
    if (tid < 5){
        float d = 0.f;
        #pragma unroll
        for (int hd=0; hd<32; hd++) d = fmaf(sho[hd], Wo0[hd*NC+tid], d);
        shx[tid] = feats[row*NC+tid] + d;     // residual on ORIGINAL x0
    }
    __syncthreads();
    if (tid == 0){
        float x[5], n0[5], mu = 0.f;
        #pragma unroll
        for (int c=0;c<5;c++){ x[c]=shx[c]; n0[c]=fabsf(x[c]); mu+=n0[c]; }
        mu *= 0.2f;
        float var = 0.f;
        #pragma unroll
        for (int c=0;c<5;c++){ float d=n0[c]-mu; var=fmaf(d,d,var); }
        var *= 0.2f;
        float sd = sqrtf(var)+1e-8f;
        float y[5];
        #pragma unroll
        for (int c=0;c<5;c++){
            float ln = (n0[c]-mu)/sd*gnF[c]+bnF[c];
            float g = gelu_t(ln);
            y[c] = (x[c]>0.f)? g : ((x[c]<0.f)? -g : 0.f);
        }
        float f0[5] = {0.f,0.f,0.f,0.f,0.f};
        #pragma unroll 4
        for (int f=0; f<NFF; f++){
            float hsum = 0.f;
            #pragma unroll
            for (int c=0;c<5;c++) hsum = fmaf(y[c], Wf1[c*NFF+f], hsum);
            float hg = gelu_t(hsum);
            #pragma unroll
            for (int c=0;c<5;c++) f0[c] = fmaf(hg, Wf2[f*NC+c], f0[c]);
        }
        #pragma unroll
        for (int c=0;c<5;c++) atomicAdd(&g_pooled[b*NC+c], x[c]+f0[c]);
    }
}

// ---------------------------------------------------------------------------
// Kernel D: head MLP -> output (2,3,3) = 18 floats
__global__ void head_mlp(const float* __restrict__ Wh1, const float* __restrict__ bh1,
                         const float* __restrict__ Wh2, const float* __restrict__ bh2,
                         float* __restrict__ out){
    __shared__ float shh[NB][128];
    int tid = threadIdx.x;   // 128 threads
    #pragma unroll
    for (int b=0; b<NB; b++){
        float sv = bh1[tid];
        #pragma unroll
        for (int c=0;c<NC;c++)
            sv = fmaf(g_pooled[b*NC+c]*(1.0f/(float)NN), Wh1[c*128+tid], sv);
        shh[b][tid] = fmaxf(sv, 0.f);
    }
    __syncthreads();
    if (tid < NB*9){
        int b = tid/9, o = tid%9;
        float sv = bh2[o];
        for (int f=0; f<128; f++) sv = fmaf(shh[b][f], Wh2[f*9+o], sv);
        out[tid] = sv;
    }
}

// ---------------------------------------------------------------------------
extern "C" void kernel_launch(void* const* d_in, const int* in_sizes, int n_in,
                              void* d_out, int out_size){
    const float* feats = (const float*)d_in[0];
    const float* coors = (const float*)d_in[1];
    const void*  adj   = d_in[2];
    const float* Wq  = (const float*)d_in[3];
    const float* Mk  = (const float*)d_in[4];
    const float* Mv  = (const float*)d_in[5];
    const float* R1  = (const float*)d_in[6];
    const float* rb1 = (const float*)d_in[7];
    const float* R2  = (const float*)d_in[8];
    const float* rb2 = (const float*)d_in[9];
    const float* Wo0 = (const float*)d_in[10];
    // d_in[11] Wo1 unused (vector channel is dead for the scalar output)
    const float* gnA = (const float*)d_in[12];
    const float* bnA = (const float*)d_in[13];
    const float* gnF = (const float*)d_in[14];
    const float* bnF = (const float*)d_in[15];
    const float* Wf1 = (const float*)d_in[16];
    const float* Wf2 = (const float*)d_in[17];
    // d_in[18] gs, d_in[19] bs unused (vector FF path dead)
    const float* Wh1 = (const float*)d_in[20];
    const float* bh1 = (const float*)d_in[21];
    const float* Wh2 = (const float*)d_in[22];
    const float* bh2 = (const float*)d_in[23];
    float* out = (float*)d_out;

    detect_adj<<<1, 256>>>((const unsigned char*)adj);
    pack_adj<<<NB*NN, 256>>>(adj);
    adjm_sq <<<NB*NN, 256>>>();
    node_pre<<<2, 256>>>(feats, Wq, Mk, Mv, gnA, bnA);
    attn_row<<<NB*NN, 256>>>(feats, coors, R1, rb1, R2, rb2, Wo0,
                             gnF, bnF, Wf1, Wf2);
    head_mlp<<<1, 128>>>(Wh1, bh1, Wh2, bh2, out);
}

// round 3
// speedup vs baseline: 1.6730x; 1.6730x over previous
#include <cuda_runtime.h>
#include <cuda_bf16.h>
#include <math.h>

// Problem constants
#define NB 2
#define NN 256
#define NC 5
#define NHID 32
#define NH 4
#define NDH 8
#define NFF 20

// Scratch (device globals: no allocation allowed)
__device__ float    g_q0[NB*NN*NHID];
__device__ float    g_yk[NB*NN*NHID];
__device__ float    g_yv[NB*NN*NHID];
__device__ unsigned g_adjbits[NB*NN*8];
__device__ float    g_pooled[NB*NC];
__device__ int      g_lanemask = 0;   // OR-only accumulation: idempotent across replays

__device__ __forceinline__ float tanh_fast(float x){
    // accurate ~1e-6, MUFU-based
    return 1.0f - 2.0f/(__expf(2.0f*x) + 1.0f);
}
__device__ __forceinline__ float gelu_t(float x){
    float x3 = x*x*x;
    float t = tanh_fast(0.7978845608028654f*(x + 0.044715f*x3));
    return 0.5f*x*(1.0f+t);
}
__device__ __forceinline__ float wredsum(float v){
    #pragma unroll
    for (int o=16;o;o>>=1) v += __shfl_xor_sync(0xffffffffu, v, o);
    return v;
}
__device__ __forceinline__ float wredmax(float v){
    #pragma unroll
    for (int o=16;o;o>>=1) v = fmaxf(v, __shfl_xor_sync(0xffffffffu, v, o));
    return v;
}
__device__ __forceinline__ int adj_mode(){
    int lm = g_lanemask;                 // bits: which byte offsets (mod 4) carry nonzeros
    if ((lm & 0xE) == 0) return 1;       // int32 0/1: only offset 0
    if ((lm & 0x3) == 0) return 2;       // float32 1.0f: only offsets 2,3
    return 0;                            // uint8
}

// ---------------------------------------------------------------------------
// Kernel 1: detect adjacency storage dtype by byte-lane signature (parallel).
__global__ void detect_adj(const unsigned char* __restrict__ a){
    int base = (blockIdx.x*256 + threadIdx.x)*4;   // 128 blocks x 256 thr x 4B = 128KB
    unsigned m = 0;
    #pragma unroll
    for (int o=0;o<4;o++) if (a[base+o]) m |= 1u << o;
    #pragma unroll
    for (int off=16; off; off>>=1) m |= __shfl_xor_sync(0xffffffffu, m, off);
    if ((threadIdx.x & 31)==0 && m) atomicOr(&g_lanemask, (int)m);
}

// ---------------------------------------------------------------------------
// Kernel 2: pack adjacency row -> bits, AND per-node norm/projections. 1 block per row.
__global__ void __launch_bounds__(256)
prep(const void* __restrict__ adjraw,
     const float* __restrict__ feats,
     const float* __restrict__ Wq, const float* __restrict__ Mk,
     const float* __restrict__ Mv,
     const float* __restrict__ gnA, const float* __restrict__ bnA){
    int row = blockIdx.x;                 // b*256+i  == node index
    int tid = threadIdx.x;                // j
    int lane = tid & 31, wp = tid >> 5;

    // pack adjacency bits for this row (dtype-agnostic)
    int mode = adj_mode();
    long idx = (long)row*NN + tid;
    bool v;
    if (mode == 1)      v = ((const int*)adjraw)[idx] != 0;
    else if (mode == 2) v = ((const float*)adjraw)[idx] != 0.f;
    else                v = ((const unsigned char*)adjraw)[idx] != 0;
    unsigned bal = __ballot_sync(0xffffffffu, v);
    if (lane == 0) g_adjbits[row*8 + wp] = bal;

    // zero pooled accumulators (10 floats)
    if (tid == 128 && row < NB*NC) g_pooled[row] = 0.f;

    // per-node scalar norm_se3 + q/k/v projections (threads 0..31, one hd each)
    if (tid < NHID){
        float xv[NC], n0[NC], mu = 0.f;
        #pragma unroll
        for (int c=0;c<NC;c++){ xv[c]=feats[row*NC+c]; n0[c]=fabsf(xv[c]); mu += n0[c]; }
        mu *= 0.2f;
        float var = 0.f;
        #pragma unroll
        for (int c=0;c<NC;c++){ float d=n0[c]-mu; var = fmaf(d,d,var); }
        var *= 0.2f;
        float sd = sqrtf(var) + 1e-8f;
        float y[NC];
        #pragma unroll
        for (int c=0;c<NC;c++){
            float ln = (n0[c]-mu)/sd * gnA[c] + bnA[c];
            float g = gelu_t(ln);
            y[c] = (xv[c] > 0.f) ? g : ((xv[c] < 0.f) ? -g : 0.f);
        }
        float q=0.f,k=0.f,w=0.f;
        #pragma unroll
        for (int c=0;c<NC;c++){
            q = fmaf(y[c], Wq[c*NHID+tid], q);
            k = fmaf(y[c], Mk[c*NHID+tid], k);
            w = fmaf(y[c], Mv[c*NHID+tid], w);
        }
        g_q0[row*NHID+tid]=q; g_yk[row*NHID+tid]=k; g_yv[row*NHID+tid]=w;
    }
}

// ---------------------------------------------------------------------------
// Kernel 3: one block per (b,i) row.
// adjm (adj|adj^2|I) in prologue -> compacted edge MLP -> masked softmax ->
// o0 -> Wo0 -> residual -> norm -> FF -> residual -> pooled atomicAdd.
__global__ void __launch_bounds__(256)
attn_row(const float* __restrict__ feats, const float* __restrict__ coors,
         const float* __restrict__ R1,  const float* __restrict__ rb1,
         const float* __restrict__ R2,  const float* __restrict__ rb2,
         const float* __restrict__ Wo0,
         const float* __restrict__ gnF, const float* __restrict__ bnF,
         const float* __restrict__ Wf1, const float* __restrict__ Wf2){
    __shared__ float shR2k[1024], shR2v[1024];                 // (32 t) x (32 hd)
    __shared__ float shR1[32], shrb1[32], shrb2k[32], shrb2v[32], shq[32];
    __shared__ unsigned shadj[8], shrow[8];
    __shared__ int shwcnt[8];
    __shared__ unsigned char shlist[256];
    __shared__ float shred[8][4];
    __shared__ float shmax[4], shsum[4];
    __shared__ float shpart[8][32];
    __shared__ float sho[32];
    __shared__ float shx[5];

    int row = blockIdx.x;
    int b = row >> 8, i = row & 255;
    int tid = threadIdx.x;
    int lane = tid & 31, wp = tid >> 5;

    for (int s=tid; s<1024; s+=256){
        int t = s >> 5, hd = s & 31;
        shR2k[s] = R2[t*384 + hd];
        shR2v[s] = R2[t*384 + 192 + hd];
    }
    if (tid < 32){
        shR1[tid]=R1[tid]; shrb1[tid]=rb1[tid];
        shrb2k[tid]=rb2[tid]; shrb2v[tid]=rb2[192+tid];
        shq[tid]=g_q0[row*NHID+tid];
    }
    if (tid < 8){
        unsigned vv0 = g_adjbits[row*8+tid];
        shrow[tid] = vv0;
        shadj[tid] = vv0 | ((tid == (i>>5)) ? (1u << (i&31)) : 0u);   // eye
    }
    __syncthreads();

    // adjm row: OR neighbors' adjacency rows (adj @ adj > 0)
    bool nb = (shrow[tid>>5] >> (tid&31)) & 1u;
    if (nb){
        int jr = (b << 8) + tid;
        #pragma unroll
        for (int w=0; w<8; w++) atomicOr(&shadj[w], g_adjbits[jr*8 + w]);
    }
    __syncthreads();

    // deterministic compaction of active j's (ascending order)
    bool ok = (shadj[tid>>5] >> (tid&31)) & 1u;
    unsigned bal = __ballot_sync(0xffffffffu, ok);
    if (lane == 0) shwcnt[wp] = __popc(bal);
    __syncthreads();
    int base = 0, M = 0;
    #pragma unroll
    for (int w=0; w<8; w++){ if (w < wp) base += shwcnt[w]; M += shwcnt[w]; }
    if (ok) shlist[base + __popc(bal & ((1u<<lane)-1u))] = (unsigned char)tid;
    __syncthreads();

    bool act = tid < M;
    int j = act ? (int)shlist[tid] : 0;

    float lg[4] = {-1e9f,-1e9f,-1e9f,-1e9f};
    float vv[32];
    #pragma unroll
    for (int hd=0; hd<32; hd++) vv[hd] = 0.f;

    float cx = coors[row*3+0], cy = coors[row*3+1], cz = coors[row*3+2];

    if (act){
        int jr = (b << 8) + j;
        float dx = cx - coors[jr*3+0];
        float dy = cy - coors[jr*3+1];
        float dz = cz - coors[jr*3+2];
        float dist = sqrtf(fmaf(dx,dx,fmaf(dy,dy,fmaf(dz,dz,1e-12f))));
        float k0[32], v0[32];
        #pragma unroll
        for (int hd=0; hd<32; hd++){ k0[hd]=shrb2k[hd]; v0[hd]=shrb2v[hd]; }
        #pragma unroll 4
        for (int t=0; t<32; t++){
            float h = fmaxf(fmaf(dist, shR1[t], shrb1[t]), 0.f);
            const float4* wk = (const float4*)&shR2k[t*32];
            const float4* wv = (const float4*)&shR2v[t*32];
            #pragma unroll
            for (int c=0; c<8; c++){
                float4 a = wk[c];
                k0[4*c+0]=fmaf(h,a.x,k0[4*c+0]); k0[4*c+1]=fmaf(h,a.y,k0[4*c+1]);
                k0[4*c+2]=fmaf(h,a.z,k0[4*c+2]); k0[4*c+3]=fmaf(h,a.w,k0[4*c+3]);
                float4 bb = wv[c];
                v0[4*c+0]=fmaf(h,bb.x,v0[4*c+0]); v0[4*c+1]=fmaf(h,bb.y,v0[4*c+1]);
                v0[4*c+2]=fmaf(h,bb.z,v0[4*c+2]); v0[4*c+3]=fmaf(h,bb.w,v0[4*c+3]);
            }
        }
        const float* ykj = g_yk + jr*NHID;
        const float* yvj = g_yv + jr*NHID;
        float l[4] = {0.f,0.f,0.f,0.f};
        #pragma unroll
        for (int hd=0; hd<32; hd++)
            l[hd>>3] = fmaf(shq[hd]*ykj[hd], k0[hd], l[hd>>3]);
        #pragma unroll
        for (int h=0; h<4; h++) lg[h] = l[h]*0.35355339059327373f;  // 1/sqrt(8)
        #pragma unroll
        for (int hd=0; hd<32; hd++) vv[hd] = v0[hd]*yvj[hd];
    }

    // masked softmax over active j's (per head)
    float m[4];
    #pragma unroll
    for (int h=0; h<4; h++) m[h] = wredmax(lg[h]);
    if (lane == 0){
        #pragma unroll
        for (int h=0; h<4; h++) shred[wp][h] = m[h];
    }
    __syncthreads();
    if (tid < 4){
        float mm = -1e9f;
        #pragma unroll
        for (int w=0; w<8; w++) mm = fmaxf(mm, shred[w][tid]);
        shmax[tid] = mm;
    }
    __syncthreads();
    float e[4];
    #pragma unroll
    for (int h=0; h<4; h++) e[h] = act ? __expf(lg[h]-shmax[h]) : 0.f;
    float s[4];
    #pragma unroll
    for (int h=0; h<4; h++) s[h] = wredsum(e[h]);
    if (lane == 0){
        #pragma unroll
        for (int h=0; h<4; h++) shred[wp][h] = s[h];
    }
    __syncthreads();
    if (tid < 4){
        float ss = 0.f;
        #pragma unroll
        for (int w=0; w<8; w++) ss += shred[w][tid];
        shsum[tid] = ss;
    }
    __syncthreads();
    float a4[4];
    #pragma unroll
    for (int h=0; h<4; h++) a4[h] = e[h]/shsum[h];

    // o0[hd] = sum_j attn * vv
    #pragma unroll
    for (int hd=0; hd<32; hd++){
        float o = a4[hd>>3]*vv[hd];
        o = wredsum(o);
        if (lane == 0) shpart[wp][hd] = o;
    }
    __syncthreads();
    if (tid < 32){
        float o = 0.f;
        #pragma unroll
        for (int w=0; w<8; w++) o += shpart[w][tid];
        sho[tid] = o;
    }
    __syncthreads();
    if (tid < 5){
        float d = 0.f;
        #pragma unroll
        for (int hd=0; hd<32; hd++) d = fmaf(sho[hd], Wo0[hd*NC+tid], d);
        shx[tid] = feats[row*NC+tid] + d;     // residual on ORIGINAL x0
    }
    __syncthreads();
    if (tid == 0){
        float x[5], n0[5], mu = 0.f;
        #pragma unroll
        for (int c=0;c<5;c++){ x[c]=shx[c]; n0[c]=fabsf(x[c]); mu+=n0[c]; }
        mu *= 0.2f;
        float var = 0.f;
        #pragma unroll
        for (int c=0;c<5;c++){ float d=n0[c]-mu; var=fmaf(d,d,var); }
        var *= 0.2f;
        float sd = sqrtf(var)+1e-8f;
        float y[5];
        #pragma unroll
        for (int c=0;c<5;c++){
            float ln = (n0[c]-mu)/sd*gnF[c]+bnF[c];
            float g = gelu_t(ln);
            y[c] = (x[c]>0.f)? g : ((x[c]<0.f)? -g : 0.f);
        }
        float f0[5] = {0.f,0.f,0.f,0.f,0.f};
        #pragma unroll 4
        for (int f=0; f<NFF; f++){
            float hsum = 0.f;
            #pragma unroll
            for (int c=0;c<5;c++) hsum = fmaf(y[c], Wf1[c*NFF+f], hsum);
            float hg = gelu_t(hsum);
            #pragma unroll
            for (int c=0;c<5;c++) f0[c] = fmaf(hg, Wf2[f*NC+c], f0[c]);
        }
        #pragma unroll
        for (int c=0;c<5;c++) atomicAdd(&g_pooled[b*NC+c], x[c]+f0[c]);
    }
}

// ---------------------------------------------------------------------------
// Kernel 4: head MLP -> output (2,3,3) = 18 floats
__global__ void head_mlp(const float* __restrict__ Wh1, const float* __restrict__ bh1,
                         const float* __restrict__ Wh2, const float* __restrict__ bh2,
                         float* __restrict__ out){
    __shared__ float shh[NB][128];
    int tid = threadIdx.x;   // 128 threads
    #pragma unroll
    for (int b=0; b<NB; b++){
        float sv = bh1[tid];
        #pragma unroll
        for (int c=0;c<NC;c++)
            sv = fmaf(g_pooled[b*NC+c]*(1.0f/(float)NN), Wh1[c*128+tid], sv);
        shh[b][tid] = fmaxf(sv, 0.f);
    }
    __syncthreads();
    if (tid < NB*9){
        int b = tid/9, o = tid%9;
        float sv = bh2[o];
        for (int f=0; f<128; f++) sv = fmaf(shh[b][f], Wh2[f*9+o], sv);
        out[tid] = sv;
    }
}

// ---------------------------------------------------------------------------
extern "C" void kernel_launch(void* const* d_in, const int* in_sizes, int n_in,
                              void* d_out, int out_size){
    const float* feats = (const float*)d_in[0];
    const float* coors = (const float*)d_in[1];
    const void*  adj   = d_in[2];
    const float* Wq  = (const float*)d_in[3];
    const float* Mk  = (const float*)d_in[4];
    const float* Mv  = (const float*)d_in[5];
    const float* R1  = (const float*)d_in[6];
    const float* rb1 = (const float*)d_in[7];
    const float* R2  = (const float*)d_in[8];
    const float* rb2 = (const float*)d_in[9];
    const float* Wo0 = (const float*)d_in[10];
    // d_in[11] Wo1 unused (vector channel dead for scalar output)
    const float* gnA = (const float*)d_in[12];
    const float* bnA = (const float*)d_in[13];
    const float* gnF = (const float*)d_in[14];
    const float* bnF = (const float*)d_in[15];
    const float* Wf1 = (const float*)d_in[16];
    const float* Wf2 = (const float*)d_in[17];
    // d_in[18] gs, d_in[19] bs unused (vector FF path dead)
    const float* Wh1 = (const float*)d_in[20];
    const float* bh1 = (const float*)d_in[21];
    const float* Wh2 = (const float*)d_in[22];
    const float* bh2 = (const float*)d_in[23];
    float* out = (float*)d_out;

    detect_adj<<<128, 256>>>((const unsigned char*)adj);
    prep<<<NB*NN, 256>>>(adj, feats, Wq, Mk, Mv, gnA, bnA);
    attn_row<<<NB*NN, 256>>>(feats, coors, R1, rb1, R2, rb2, Wo0,
                             gnF, bnF, Wf1, Wf2);
    head_mlp<<<1, 128>>>(Wh1, bh1, Wh2, bh2, out);
}